// round 2
// baseline (speedup 1.0000x reference)
#include <cuda_runtime.h>
#include <cstdint>
#include <cstddef>

#define N_NODES 100000
#define N_EDGES 600000
#define DMODEL  128
#define NREL    50

// Scratch: transformed features per type [4][N][128] and gate pre-activations [4][N]
__device__ float g_T[(size_t)4 * N_NODES * DMODEL];
__device__ float g_G[4 * N_NODES];

__device__ __forceinline__ unsigned f2tf32(float x) {
    unsigned r;
    asm("cvt.rna.tf32.f32 %0, %1;" : "=r"(r) : "f"(x));
    return r;
}

#define MMA_TF32(c, a0, a1, a2, a3, b0, b1)                                  \
    asm volatile("mma.sync.aligned.m16n8k8.row.col.f32.tf32.tf32.f32 "       \
                 "{%0,%1,%2,%3}, {%4,%5,%6,%7}, {%8,%9}, {%0,%1,%2,%3};"     \
                 : "+f"(c[0]), "+f"(c[1]), "+f"(c[2]), "+f"(c[3])            \
                 : "r"(a0), "r"(a1), "r"(a2), "r"(a3), "r"(b0), "r"(b1))

// One block: 128-node tile x all 4 types. 256 threads = 8 warps, each warp owns
// 16 rows x 128 cols of output. tf32 MMA with 3-pass hi/lo split (~fp32 accuracy).
__global__ __launch_bounds__(256) void transform_kernel(
    const float* __restrict__ inp,
    const float* __restrict__ W0, const float* __restrict__ W1,
    const float* __restrict__ W2, const float* __restrict__ W3,
    const float* __restrict__ G0, const float* __restrict__ G1,
    const float* __restrict__ G2, const float* __restrict__ G3)
{
    extern __shared__ float sm[];
    float* As = sm;                // [128][132] input tile (padded pitch)
    float* Ws = sm + 128 * 132;    // [128][132] weight tile
    const int tid  = threadIdx.x;
    const int warp = tid >> 5, lane = tid & 31;
    const int gid  = lane >> 2;    // groupID (0..7)
    const int tg   = lane & 3;     // thread-in-group (0..3)
    const int m0   = blockIdx.x * 128;

    // Load input tile (float4), zero-pad past N_NODES
    for (int i = tid; i < 128 * 32; i += 256) {
        int row = i >> 5, c4 = i & 31;
        float4 v = make_float4(0.f, 0.f, 0.f, 0.f);
        int gr = m0 + row;
        if (gr < N_NODES) v = reinterpret_cast<const float4*>(inp)[(size_t)gr * 32 + c4];
        float* dst = &As[row * 132 + c4 * 4];
        dst[0] = v.x; dst[1] = v.y; dst[2] = v.z; dst[3] = v.w;
    }

    const float* const Wt[4] = {W0, W1, W2, W3};

    #pragma unroll
    for (int t = 0; t < 4; t++) {
        __syncthreads();
        // Load weight tile for this type
        for (int i = tid; i < 128 * 32; i += 256) {
            int row = i >> 5, c4 = i & 31;
            float4 v = reinterpret_cast<const float4*>(Wt[t])[row * 32 + c4];
            float* dst = &Ws[row * 132 + c4 * 4];
            dst[0] = v.x; dst[1] = v.y; dst[2] = v.z; dst[3] = v.w;
        }
        __syncthreads();

        float acc[16][4];
        #pragma unroll
        for (int j = 0; j < 16; j++) { acc[j][0] = acc[j][1] = acc[j][2] = acc[j][3] = 0.f; }

        const int mrow = warp * 16;
        for (int k0 = 0; k0 < 128; k0 += 8) {
            float af0 = As[(mrow + gid)     * 132 + k0 + tg];
            float af1 = As[(mrow + gid + 8) * 132 + k0 + tg];
            float af2 = As[(mrow + gid)     * 132 + k0 + tg + 4];
            float af3 = As[(mrow + gid + 8) * 132 + k0 + tg + 4];
            unsigned ah0 = f2tf32(af0), ah1 = f2tf32(af1), ah2 = f2tf32(af2), ah3 = f2tf32(af3);
            unsigned al0 = f2tf32(af0 - __uint_as_float(ah0));
            unsigned al1 = f2tf32(af1 - __uint_as_float(ah1));
            unsigned al2 = f2tf32(af2 - __uint_as_float(ah2));
            unsigned al3 = f2tf32(af3 - __uint_as_float(ah3));
            #pragma unroll
            for (int j = 0; j < 16; j++) {
                float bf0 = Ws[(j * 8 + gid) * 132 + k0 + tg];
                float bf1 = Ws[(j * 8 + gid) * 132 + k0 + tg + 4];
                unsigned bh0 = f2tf32(bf0), bh1 = f2tf32(bf1);
                unsigned bl0 = f2tf32(bf0 - __uint_as_float(bh0));
                unsigned bl1 = f2tf32(bf1 - __uint_as_float(bh1));
                MMA_TF32(acc[j], al0, al1, al2, al3, bh0, bh1);
                MMA_TF32(acc[j], ah0, ah1, ah2, ah3, bl0, bl1);
                MMA_TF32(acc[j], ah0, ah1, ah2, ah3, bh0, bh1);
            }
        }

        // Store D fragments: c0/c1 -> (row, 2*tg / +1), c2/c3 -> (row+8, ...)
        float* Tout = g_T + (size_t)t * N_NODES * DMODEL;
        #pragma unroll
        for (int j = 0; j < 16; j++) {
            int col = j * 8 + 2 * tg;
            int r0 = m0 + mrow + gid;
            int r1 = r0 + 8;
            if (r0 < N_NODES) {
                float2 v = make_float2(acc[j][0], acc[j][1]);
                *reinterpret_cast<float2*>(&Tout[(size_t)r0 * DMODEL + col]) = v;
            }
            if (r1 < N_NODES) {
                float2 v = make_float2(acc[j][2], acc[j][3]);
                *reinterpret_cast<float2*>(&Tout[(size_t)r1 * DMODEL + col]) = v;
            }
        }
    }

    __syncthreads();
    // Gate pre-activations: 512 (node, type) dots of length 128, from smem input tile
    for (int i = tid; i < 512; i += 256) {
        int node = i >> 2, t = i & 3;
        int gr = m0 + node;
        if (gr < N_NODES) {
            const float* gw = (t == 0) ? G0 : (t == 1) ? G1 : (t == 2) ? G2 : G3;
            float s = 0.f;
            #pragma unroll 8
            for (int k = 0; k < 128; k++) s += As[node * 132 + k] * gw[k];
            g_G[t * N_NODES + gr] = s;
        }
    }
}

// One warp per edge: gather T row (512B), add relation bias, gate, vector-reduce
// into out[tgt]. red.global.add.v4.f32 = 1 reduction per lane (16B each).
__global__ __launch_bounds__(256) void edge_kernel(
    const int* __restrict__ deprel, const int* __restrict__ deparc,
    const int* __restrict__ eidx,
    const float* __restrict__ b_in, const float* __restrict__ b_out,
    const float* __restrict__ bg_in, const float* __restrict__ bg_out,
    float* __restrict__ out)
{
    int e = (int)((blockIdx.x * blockDim.x + threadIdx.x) >> 5);
    if (e >= N_EDGES) return;
    int lane = threadIdx.x & 31;

    int t   = deparc[e];
    int rel = deprel[e];
    int src = eidx[e];
    int tgt = eidx[N_EDGES + e];

    const float* trow = g_T + ((size_t)t * N_NODES + src) * DMODEL;
    float4 v = reinterpret_cast<const float4*>(trow)[lane];
    float gpre = g_G[t * N_NODES + src];

    float4 b = make_float4(0.f, 0.f, 0.f, 0.f);
    if (t == 0) {
        b = reinterpret_cast<const float4*>(b_in)[rel * 32 + lane];
        gpre += bg_in[rel];
    } else if (t == 1) {
        b = reinterpret_cast<const float4*>(b_out)[rel * 32 + lane];
        gpre += bg_out[rel];
    }

    float g = 1.f / (1.f + __expf(-gpre));
    float4 r;
    r.x = (v.x + b.x) * g;
    r.y = (v.y + b.y) * g;
    r.z = (v.z + b.z) * g;
    r.w = (v.w + b.w) * g;

    float* dst = out + (size_t)tgt * DMODEL + lane * 4;
    asm volatile("red.global.add.v4.f32 [%0], {%1,%2,%3,%4};"
                 :: "l"(dst), "f"(r.x), "f"(r.y), "f"(r.z), "f"(r.w)
                 : "memory");
}

extern "C" void kernel_launch(void* const* d_in, const int* in_sizes, int n_in,
                              void* d_out, int out_size)
{
    const float* inp       = (const float*)d_in[0];
    const int*   deprel    = (const int*)d_in[1];
    const int*   deparc    = (const int*)d_in[2];
    const int*   eidx      = (const int*)d_in[3];
    const float* V_in      = (const float*)d_in[4];
    const float* b_in      = (const float*)d_in[5];
    const float* V_in_g    = (const float*)d_in[6];
    const float* b_in_g    = (const float*)d_in[7];
    const float* V_out     = (const float*)d_in[8];
    const float* b_out     = (const float*)d_in[9];
    const float* V_out_g   = (const float*)d_in[10];
    const float* b_out_g   = (const float*)d_in[11];
    const float* W_self    = (const float*)d_in[12];
    const float* W_self_g  = (const float*)d_in[13];
    const float* W_norel   = (const float*)d_in[14];
    const float* W_norel_g = (const float*)d_in[15];
    float* out = (float*)d_out;

    const int smem = 2 * 128 * 132 * 4;  // 135168 bytes
    cudaFuncSetAttribute(transform_kernel,
                         cudaFuncAttributeMaxDynamicSharedMemorySize, smem);

    cudaMemsetAsync(d_out, 0, (size_t)out_size * sizeof(float));

    transform_kernel<<<(N_NODES + 127) / 128, 256, smem>>>(
        inp, V_in, V_out, W_self, W_norel, V_in_g, V_out_g, W_self_g, W_norel_g);

    edge_kernel<<<(N_EDGES * 32) / 256, 256>>>(
        deprel, deparc, eidx, b_in, b_out, b_in_g, b_out_g, out);
}

// round 3
// speedup vs baseline: 1.4878x; 1.4878x over previous
#include <cuda_runtime.h>
#include <cstdint>
#include <cstddef>

#define N_NODES 100000
#define N_EDGES 600000
#define DMODEL  128
#define NREL    50

// Scratch: transformed features per type [4][N][128] and gate pre-activations [4][N]
__device__ float g_T[(size_t)4 * N_NODES * DMODEL];
__device__ float g_G[4 * N_NODES];

__device__ __forceinline__ unsigned f2tf32(float x) {
    unsigned r;
    asm("cvt.rna.tf32.f32 %0, %1;" : "=r"(r) : "f"(x));
    return r;
}

#define MMA_TF32(c, a0, a1, a2, a3, b0, b1)                                  \
    asm volatile("mma.sync.aligned.m16n8k8.row.col.f32.tf32.tf32.f32 "       \
                 "{%0,%1,%2,%3}, {%4,%5,%6,%7}, {%8,%9}, {%0,%1,%2,%3};"     \
                 : "+f"(c[0]), "+f"(c[1]), "+f"(c[2]), "+f"(c[3])            \
                 : "r"(a0), "r"(a1), "r"(a2), "r"(a3), "r"(b0), "r"(b1))

// One block: 128-node tile x all 4 types. 256 threads = 8 warps, each warp owns
// 16 rows x 128 cols of output. Single-pass tf32 (rel err ~3e-4 << 1e-3 gate).
// Tiles pre-converted to tf32 in smem: inner loop is pure LDS + HMMA.
__global__ __launch_bounds__(256) void transform_kernel(
    const float* __restrict__ inp,
    const float* __restrict__ W0, const float* __restrict__ W1,
    const float* __restrict__ W2, const float* __restrict__ W3,
    const float* __restrict__ G0, const float* __restrict__ G1,
    const float* __restrict__ G2, const float* __restrict__ G3)
{
    extern __shared__ float sm[];
    float*    Af  = sm;                                    // [128][132] fp32 input (gates)
    unsigned* AsU = (unsigned*)(sm + 128 * 132);           // [128][132] tf32 input
    unsigned* WsU = (unsigned*)(sm + 2 * 128 * 132);       // [128][132] tf32 weights
    const int tid  = threadIdx.x;
    const int warp = tid >> 5, lane = tid & 31;
    const int gid  = lane >> 2;    // groupID (0..7)
    const int tg   = lane & 3;     // thread-in-group (0..3)
    const int m0   = blockIdx.x * 128;

    // Load input tile (float4), zero-pad past N_NODES; keep fp32 + tf32 copies
    for (int i = tid; i < 128 * 32; i += 256) {
        int row = i >> 5, c4 = i & 31;
        float4 v = make_float4(0.f, 0.f, 0.f, 0.f);
        int gr = m0 + row;
        if (gr < N_NODES) v = reinterpret_cast<const float4*>(inp)[(size_t)gr * 32 + c4];
        int o = row * 132 + c4 * 4;
        Af[o] = v.x; Af[o+1] = v.y; Af[o+2] = v.z; Af[o+3] = v.w;
        AsU[o]   = f2tf32(v.x); AsU[o+1] = f2tf32(v.y);
        AsU[o+2] = f2tf32(v.z); AsU[o+3] = f2tf32(v.w);
    }

    const float* const Wt[4] = {W0, W1, W2, W3};

    #pragma unroll
    for (int t = 0; t < 4; t++) {
        __syncthreads();
        // Load + convert weight tile for this type
        for (int i = tid; i < 128 * 32; i += 256) {
            int row = i >> 5, c4 = i & 31;
            float4 v = reinterpret_cast<const float4*>(Wt[t])[row * 32 + c4];
            int o = row * 132 + c4 * 4;
            WsU[o]   = f2tf32(v.x); WsU[o+1] = f2tf32(v.y);
            WsU[o+2] = f2tf32(v.z); WsU[o+3] = f2tf32(v.w);
        }
        __syncthreads();

        float acc[16][4];
        #pragma unroll
        for (int j = 0; j < 16; j++) { acc[j][0] = acc[j][1] = acc[j][2] = acc[j][3] = 0.f; }

        const int mrow = warp * 16;
        #pragma unroll 4
        for (int k0 = 0; k0 < 128; k0 += 8) {
            unsigned a0 = AsU[(mrow + gid)     * 132 + k0 + tg];
            unsigned a1 = AsU[(mrow + gid + 8) * 132 + k0 + tg];
            unsigned a2 = AsU[(mrow + gid)     * 132 + k0 + tg + 4];
            unsigned a3 = AsU[(mrow + gid + 8) * 132 + k0 + tg + 4];
            #pragma unroll
            for (int j = 0; j < 16; j++) {
                unsigned b0 = WsU[(j * 8 + gid) * 132 + k0 + tg];
                unsigned b1 = WsU[(j * 8 + gid) * 132 + k0 + tg + 4];
                MMA_TF32(acc[j], a0, a1, a2, a3, b0, b1);
            }
        }

        // Store D fragments: c0/c1 -> (row, 2*tg / +1), c2/c3 -> (row+8, ...)
        float* Tout = g_T + (size_t)t * N_NODES * DMODEL;
        #pragma unroll
        for (int j = 0; j < 16; j++) {
            int col = j * 8 + 2 * tg;
            int r0 = m0 + mrow + gid;
            int r1 = r0 + 8;
            if (r0 < N_NODES) {
                float2 v = make_float2(acc[j][0], acc[j][1]);
                *reinterpret_cast<float2*>(&Tout[(size_t)r0 * DMODEL + col]) = v;
            }
            if (r1 < N_NODES) {
                float2 v = make_float2(acc[j][2], acc[j][3]);
                *reinterpret_cast<float2*>(&Tout[(size_t)r1 * DMODEL + col]) = v;
            }
        }
    }

    __syncthreads();
    // Gate pre-activations in fp32: 512 (node, type) dots of length 128
    for (int i = tid; i < 512; i += 256) {
        int node = i >> 2, t = i & 3;
        int gr = m0 + node;
        if (gr < N_NODES) {
            const float* gw = (t == 0) ? G0 : (t == 1) ? G1 : (t == 2) ? G2 : G3;
            float s = 0.f;
            #pragma unroll 8
            for (int k = 0; k < 128; k++) s += Af[node * 132 + k] * gw[k];
            g_G[t * N_NODES + gr] = s;
        }
    }
}

// One warp per edge: gather T row (512B), add relation bias, gate, vector-reduce
// into out[tgt]. red.global.add.v4.f32 = 1 reduction per lane (16B each).
__global__ __launch_bounds__(256) void edge_kernel(
    const int* __restrict__ deprel, const int* __restrict__ deparc,
    const int* __restrict__ eidx,
    const float* __restrict__ b_in, const float* __restrict__ b_out,
    const float* __restrict__ bg_in, const float* __restrict__ bg_out,
    float* __restrict__ out)
{
    int e = (int)((blockIdx.x * blockDim.x + threadIdx.x) >> 5);
    if (e >= N_EDGES) return;
    int lane = threadIdx.x & 31;

    int t   = deparc[e];
    int rel = deprel[e];
    int src = eidx[e];
    int tgt = eidx[N_EDGES + e];

    const float* trow = g_T + ((size_t)t * N_NODES + src) * DMODEL;
    float4 v = reinterpret_cast<const float4*>(trow)[lane];
    float gpre = g_G[t * N_NODES + src];

    float4 b = make_float4(0.f, 0.f, 0.f, 0.f);
    if (t == 0) {
        b = reinterpret_cast<const float4*>(b_in)[rel * 32 + lane];
        gpre += bg_in[rel];
    } else if (t == 1) {
        b = reinterpret_cast<const float4*>(b_out)[rel * 32 + lane];
        gpre += bg_out[rel];
    }

    float g = 1.f / (1.f + __expf(-gpre));
    float4 r;
    r.x = (v.x + b.x) * g;
    r.y = (v.y + b.y) * g;
    r.z = (v.z + b.z) * g;
    r.w = (v.w + b.w) * g;

    float* dst = out + (size_t)tgt * DMODEL + lane * 4;
    asm volatile("red.global.add.v4.f32 [%0], {%1,%2,%3,%4};"
                 :: "l"(dst), "f"(r.x), "f"(r.y), "f"(r.z), "f"(r.w)
                 : "memory");
}

extern "C" void kernel_launch(void* const* d_in, const int* in_sizes, int n_in,
                              void* d_out, int out_size)
{
    const float* inp       = (const float*)d_in[0];
    const int*   deprel    = (const int*)d_in[1];
    const int*   deparc    = (const int*)d_in[2];
    const int*   eidx      = (const int*)d_in[3];
    const float* V_in      = (const float*)d_in[4];
    const float* b_in      = (const float*)d_in[5];
    const float* V_in_g    = (const float*)d_in[6];
    const float* b_in_g    = (const float*)d_in[7];
    const float* V_out     = (const float*)d_in[8];
    const float* b_out     = (const float*)d_in[9];
    const float* V_out_g   = (const float*)d_in[10];
    const float* b_out_g   = (const float*)d_in[11];
    const float* W_self    = (const float*)d_in[12];
    const float* W_self_g  = (const float*)d_in[13];
    const float* W_norel   = (const float*)d_in[14];
    const float* W_norel_g = (const float*)d_in[15];
    float* out = (float*)d_out;

    const int smem = 3 * 128 * 132 * 4;  // 202752 bytes
    cudaFuncSetAttribute(transform_kernel,
                         cudaFuncAttributeMaxDynamicSharedMemorySize, smem);

    cudaMemsetAsync(d_out, 0, (size_t)out_size * sizeof(float));

    transform_kernel<<<(N_NODES + 127) / 128, 256, smem>>>(
        inp, V_in, V_out, W_self, W_norel, V_in_g, V_out_g, W_self_g, W_norel_g);

    edge_kernel<<<(N_EDGES * 32) / 256, 256>>>(
        deprel, deparc, eidx, b_in, b_out, b_in_g, b_out_g, out);
}

// round 5
// speedup vs baseline: 1.6831x; 1.1313x over previous
#include <cuda_runtime.h>
#include <cuda_fp16.h>
#include <cstdint>
#include <cstddef>

#define N_NODES 100000
#define N_EDGES 600000
#define DMODEL  128
#define NREL    50

// Scratch: transformed features per type [4][N][128] and gate pre-activations [4][N]
__device__ float g_T[(size_t)4 * N_NODES * DMODEL];
__device__ float g_G[4 * N_NODES];

#define MMA_F16(c, a0, a1, a2, a3, b0, b1)                                   \
    asm volatile("mma.sync.aligned.m16n8k16.row.col.f32.f16.f16.f32 "        \
                 "{%0,%1,%2,%3}, {%4,%5,%6,%7}, {%8,%9}, {%0,%1,%2,%3};"     \
                 : "+f"(c[0]), "+f"(c[1]), "+f"(c[2]), "+f"(c[3])            \
                 : "r"(a0), "r"(a1), "r"(a2), "r"(a3), "r"(b0), "r"(b1))

// One block: 128-node tile x all 4 types. 256 threads = 8 warps, each warp owns
// 16 rows x 128 cols of output. fp16 m16n8k16, fp32 accum (rel err ~3e-4).
// Tiles pre-converted to half in smem, pitch 136 (bank-conflict-free).
__global__ __launch_bounds__(256) void transform_kernel(
    const float* __restrict__ inp,
    const float* __restrict__ W0, const float* __restrict__ W1,
    const float* __restrict__ W2, const float* __restrict__ W3,
    const float* __restrict__ G0, const float* __restrict__ G1,
    const float* __restrict__ G2, const float* __restrict__ G3)
{
    extern __shared__ float sm[];
    float* Af = sm;                                   // [128][132] fp32 (gates)
    __half* Ah = (__half*)(sm + 128 * 132);           // [128][136] half input
    __half* Wh = Ah + 128 * 136;                      // [128][136] half weights
    const int tid  = threadIdx.x;
    const int warp = tid >> 5, lane = tid & 31;
    const int gid  = lane >> 2;    // groupID (0..7)
    const int tg   = lane & 3;     // thread-in-group (0..3)
    const int m0   = blockIdx.x * 128;

    // Load input tile (float2 pairs), zero-pad; keep fp32 + half copies
    for (int i = tid; i < 128 * 64; i += 256) {
        int row = i >> 6, cp = i & 63;
        int gr = m0 + row;
        float2 v = make_float2(0.f, 0.f);
        if (gr < N_NODES) v = reinterpret_cast<const float2*>(inp)[(size_t)gr * 64 + cp];
        Af[row * 132 + 2 * cp]     = v.x;
        Af[row * 132 + 2 * cp + 1] = v.y;
        *reinterpret_cast<__half2*>(&Ah[row * 136 + 2 * cp]) = __float22half2_rn(v);
    }

    const float* const Wt[4] = {W0, W1, W2, W3};

    #pragma unroll
    for (int t = 0; t < 4; t++) {
        __syncthreads();
        // Load + convert weight tile for this type ([out n][in k] row-major)
        for (int i = tid; i < 128 * 64; i += 256) {
            int row = i >> 6, cp = i & 63;
            float2 v = reinterpret_cast<const float2*>(Wt[t])[row * 64 + cp];
            *reinterpret_cast<__half2*>(&Wh[row * 136 + 2 * cp]) = __float22half2_rn(v);
        }
        __syncthreads();

        float acc[16][4];
        #pragma unroll
        for (int j = 0; j < 16; j++) { acc[j][0] = acc[j][1] = acc[j][2] = acc[j][3] = 0.f; }

        const int mrow = warp * 16;
        #pragma unroll
        for (int k0 = 0; k0 < 128; k0 += 16) {
            // A fragment: a0=(row gid, k 2tg..+1), a1=(gid+8, same), a2/a3 = +8 in k
            unsigned a0 = *(const unsigned*)&Ah[(mrow + gid)     * 136 + k0 + 2 * tg];
            unsigned a1 = *(const unsigned*)&Ah[(mrow + gid + 8) * 136 + k0 + 2 * tg];
            unsigned a2 = *(const unsigned*)&Ah[(mrow + gid)     * 136 + k0 + 2 * tg + 8];
            unsigned a3 = *(const unsigned*)&Ah[(mrow + gid + 8) * 136 + k0 + 2 * tg + 8];
            #pragma unroll
            for (int j = 0; j < 16; j++) {
                // B fragment: b0=(n j*8+gid, k 2tg..+1), b1 = +8 in k
                unsigned b0 = *(const unsigned*)&Wh[(j * 8 + gid) * 136 + k0 + 2 * tg];
                unsigned b1 = *(const unsigned*)&Wh[(j * 8 + gid) * 136 + k0 + 2 * tg + 8];
                MMA_F16(acc[j], a0, a1, a2, a3, b0, b1);
            }
        }

        // Store D fragments: c0/c1 -> (row, 2*tg / +1), c2/c3 -> (row+8, ...)
        float* Tout = g_T + (size_t)t * N_NODES * DMODEL;
        #pragma unroll
        for (int j = 0; j < 16; j++) {
            int col = j * 8 + 2 * tg;
            int r0 = m0 + mrow + gid;
            int r1 = r0 + 8;
            if (r0 < N_NODES) {
                float2 v = make_float2(acc[j][0], acc[j][1]);
                *reinterpret_cast<float2*>(&Tout[(size_t)r0 * DMODEL + col]) = v;
            }
            if (r1 < N_NODES) {
                float2 v = make_float2(acc[j][2], acc[j][3]);
                *reinterpret_cast<float2*>(&Tout[(size_t)r1 * DMODEL + col]) = v;
            }
        }
    }

    __syncthreads();
    // Gate pre-activations in fp32: 512 (node, type) dots of length 128
    for (int i = tid; i < 512; i += 256) {
        int node = i >> 2, t = i & 3;
        int gr = m0 + node;
        if (gr < N_NODES) {
            const float* gw = (t == 0) ? G0 : (t == 1) ? G1 : (t == 2) ? G2 : G3;
            float s = 0.f;
            #pragma unroll 8
            for (int k = 0; k < 128; k++) s += Af[node * 132 + k] * gw[k];
            g_G[t * N_NODES + gr] = s;
        }
    }
}

// 2 edges per warp (independent in-flight gathers for latency hiding).
// Per edge: gather T row (512B), add relation bias, gate, red.global.add.v4.f32.
#define EDGES_PER_WARP 2
__global__ __launch_bounds__(256) void edge_kernel(
    const int* __restrict__ deprel, const int* __restrict__ deparc,
    const int* __restrict__ eidx,
    const float* __restrict__ b_in, const float* __restrict__ b_out,
    const float* __restrict__ bg_in, const float* __restrict__ bg_out,
    float* __restrict__ out)
{
    int w = (int)((blockIdx.x * blockDim.x + threadIdx.x) >> 5);
    int lane = threadIdx.x & 31;
    int e0 = w * EDGES_PER_WARP;

    int   t[EDGES_PER_WARP], rel[EDGES_PER_WARP], tgt[EDGES_PER_WARP];
    float4 v[EDGES_PER_WARP];
    float  gpre[EDGES_PER_WARP];
    bool   ok[EDGES_PER_WARP];

    #pragma unroll
    for (int q = 0; q < EDGES_PER_WARP; q++) {
        int e = e0 + q;
        ok[q] = (e < N_EDGES);
        if (ok[q]) {
            t[q]   = __ldg(&deparc[e]);
            rel[q] = __ldg(&deprel[e]);
            int src = __ldg(&eidx[e]);
            tgt[q] = __ldg(&eidx[N_EDGES + e]);
            const float* trow = g_T + ((size_t)t[q] * N_NODES + src) * DMODEL;
            v[q] = reinterpret_cast<const float4*>(trow)[lane];
            gpre[q] = g_G[t[q] * N_NODES + src];
        }
    }

    #pragma unroll
    for (int q = 0; q < EDGES_PER_WARP; q++) {
        if (!ok[q]) continue;
        float4 b = make_float4(0.f, 0.f, 0.f, 0.f);
        if (t[q] == 0) {
            b = reinterpret_cast<const float4*>(b_in)[rel[q] * 32 + lane];
            gpre[q] += bg_in[rel[q]];
        } else if (t[q] == 1) {
            b = reinterpret_cast<const float4*>(b_out)[rel[q] * 32 + lane];
            gpre[q] += bg_out[rel[q]];
        }
        float g = 1.f / (1.f + __expf(-gpre[q]));
        float4 r;
        r.x = (v[q].x + b.x) * g;
        r.y = (v[q].y + b.y) * g;
        r.z = (v[q].z + b.z) * g;
        r.w = (v[q].w + b.w) * g;
        float* dst = out + (size_t)tgt[q] * DMODEL + lane * 4;
        asm volatile("red.global.add.v4.f32 [%0], {%1,%2,%3,%4};"
                     :: "l"(dst), "f"(r.x), "f"(r.y), "f"(r.z), "f"(r.w)
                     : "memory");
    }
}

extern "C" void kernel_launch(void* const* d_in, const int* in_sizes, int n_in,
                              void* d_out, int out_size)
{
    const float* inp       = (const float*)d_in[0];
    const int*   deprel    = (const int*)d_in[1];
    const int*   deparc    = (const int*)d_in[2];
    const int*   eidx      = (const int*)d_in[3];
    const float* V_in      = (const float*)d_in[4];
    const float* b_in      = (const float*)d_in[5];
    const float* V_in_g    = (const float*)d_in[6];
    const float* b_in_g    = (const float*)d_in[7];
    const float* V_out     = (const float*)d_in[8];
    const float* b_out     = (const float*)d_in[9];
    const float* V_out_g   = (const float*)d_in[10];
    const float* b_out_g   = (const float*)d_in[11];
    const float* W_self    = (const float*)d_in[12];
    const float* W_self_g  = (const float*)d_in[13];
    const float* W_norel   = (const float*)d_in[14];
    const float* W_norel_g = (const float*)d_in[15];
    float* out = (float*)d_out;

    // smem: Af 128*132*4 + (Ah + Wh) 2*128*136*2 = 67584 + 69632 = 137216 B
    const int smem = 128 * 132 * 4 + 2 * 128 * 136 * 2;
    cudaFuncSetAttribute(transform_kernel,
                         cudaFuncAttributeMaxDynamicSharedMemorySize, smem);

    cudaMemsetAsync(d_out, 0, (size_t)out_size * sizeof(float));

    transform_kernel<<<(N_NODES + 127) / 128, 256, smem>>>(
        inp, V_in, V_out, W_self, W_norel, V_in_g, V_out_g, W_self_g, W_norel_g);

    const int warps_needed = (N_EDGES + EDGES_PER_WARP - 1) / EDGES_PER_WARP;
    edge_kernel<<<(warps_needed * 32 + 255) / 256, 256>>>(
        deprel, deparc, eidx, b_in, b_out, b_in_g, b_out_g, out);
}

// round 9
// speedup vs baseline: 2.1696x; 1.2891x over previous
#include <cuda_runtime.h>
#include <cuda_fp16.h>
#include <cstdint>
#include <cstddef>

#define N_NODES 100000
#define N_EDGES 600000
#define DMODEL  128
#define NREL    50
#define N_PAD   100096          // 782 tiles * 128

// Scratch
__device__ float  g_T[(size_t)4 * N_NODES * DMODEL];   // transformed features [4][N][128]
__device__ float  g_G[4 * N_NODES];                    // gate pre-activations
__device__ __half g_inph[(size_t)N_PAD * DMODEL];      // fp16 input copy (padded rows)
__device__ __half g_Wh4[4 * 128 * 136];                // fp16 weights, padded pitch 136

#define MMA_F16(c, a0, a1, a2, a3, b0, b1)                                   \
    asm volatile("mma.sync.aligned.m16n8k16.row.col.f32.f16.f16.f32 "        \
                 "{%0,%1,%2,%3}, {%4,%5,%6,%7}, {%8,%9}, {%0,%1,%2,%3};"     \
                 : "+f"(c[0]), "+f"(c[1]), "+f"(c[2]), "+f"(c[3])            \
                 : "r"(a0), "r"(a1), "r"(a2), "r"(a3), "r"(b0), "r"(b1))

__device__ __forceinline__ uint32_t smem_u32(const void* p) {
    uint32_t a;
    asm("{ .reg .u64 t; cvta.to.shared.u64 t, %1; cvt.u32.u64 %0, t; }" : "=r"(a) : "l"(p));
    return a;
}
__device__ __forceinline__ void cpa16(uint32_t dst, const void* src) {
    asm volatile("cp.async.cg.shared.global [%0], [%1], 16;" :: "r"(dst), "l"(src));
}
#define CPA_COMMIT() asm volatile("cp.async.commit_group;" ::: "memory")
#define CPA_WAIT0()  asm volatile("cp.async.wait_group 0;" ::: "memory")

// ---- prep 1: per-node fp32 gate dots + fp16 input copy (single pass over inp) ----
__global__ __launch_bounds__(256) void prep_nodes_kernel(
    const float* __restrict__ inp,
    const float* __restrict__ G0, const float* __restrict__ G1,
    const float* __restrict__ G2, const float* __restrict__ G3)
{
    int warp = threadIdx.x >> 5, lane = threadIdx.x & 31;
    int row = blockIdx.x * 8 + warp;
    if (row >= N_NODES) return;

    float4 v  = reinterpret_cast<const float4*>(inp)[row * 32 + lane];
    float4 w0 = reinterpret_cast<const float4*>(G0)[lane];
    float4 w1 = reinterpret_cast<const float4*>(G1)[lane];
    float4 w2 = reinterpret_cast<const float4*>(G2)[lane];
    float4 w3 = reinterpret_cast<const float4*>(G3)[lane];
    float d0 = v.x * w0.x + v.y * w0.y + v.z * w0.z + v.w * w0.w;
    float d1 = v.x * w1.x + v.y * w1.y + v.z * w1.z + v.w * w1.w;
    float d2 = v.x * w2.x + v.y * w2.y + v.z * w2.z + v.w * w2.w;
    float d3 = v.x * w3.x + v.y * w3.y + v.z * w3.z + v.w * w3.w;
    #pragma unroll
    for (int off = 16; off; off >>= 1) {
        d0 += __shfl_xor_sync(0xffffffff, d0, off);
        d1 += __shfl_xor_sync(0xffffffff, d1, off);
        d2 += __shfl_xor_sync(0xffffffff, d2, off);
        d3 += __shfl_xor_sync(0xffffffff, d3, off);
    }
    if (lane == 0) {
        g_G[0 * N_NODES + row] = d0;
        g_G[1 * N_NODES + row] = d1;
        g_G[2 * N_NODES + row] = d2;
        g_G[3 * N_NODES + row] = d3;
    }
    __half2 h0 = __float22half2_rn(make_float2(v.x, v.y));
    __half2 h1 = __float22half2_rn(make_float2(v.z, v.w));
    uint2 pk = make_uint2(*(uint32_t*)&h0, *(uint32_t*)&h1);
    *reinterpret_cast<uint2*>(&g_inph[(size_t)row * DMODEL + lane * 4]) = pk;
}

// ---- prep 2: weights -> fp16, padded pitch-136 layout ----
__global__ __launch_bounds__(256) void prep_weights_kernel(
    const float* __restrict__ W0, const float* __restrict__ W1,
    const float* __restrict__ W2, const float* __restrict__ W3)
{
    for (int e = blockIdx.x * 256 + threadIdx.x; e < 4 * 128 * 64; e += gridDim.x * 256) {
        int t = e >> 13, r = (e >> 6) & 127, cp = e & 63;
        const float* W = (t == 0) ? W0 : (t == 1) ? W1 : (t == 2) ? W2 : W3;
        float2 v = reinterpret_cast<const float2*>(W)[r * 64 + cp];
        __half2 h = __float22half2_rn(v);
        *reinterpret_cast<__half2*>(&g_Wh4[t * 128 * 136 + r * 136 + 2 * cp]) = h;
    }
}

// ---- transform: 512 threads, cp.async double-buffered weights ----
// Each CTA: 128-row tile x 4 types. 16 warps: warp (wq, wn) covers 16 rows x 64 cols.
__global__ __launch_bounds__(512, 1) void transform_kernel()
{
    extern __shared__ char sm[];
    __half* Ah  = (__half*)sm;                     // [128][136]
    __half* Wb0 = (__half*)(sm + 34816);
    __half* Wb1 = (__half*)(sm + 69632);
    const uint32_t sA  = smem_u32(Ah);
    const uint32_t sW0 = smem_u32(Wb0);
    const uint32_t sW1 = smem_u32(Wb1);

    const int tid  = threadIdx.x;
    const int warp = tid >> 5, lane = tid & 31;
    const int gid  = lane >> 2, tg = lane & 3;
    const int m0   = blockIdx.x * 128;
    const int lrow = tid & 127;             // loader row
    const int lch0 = tid >> 7;              // loader chunk start (0..3)

    // Issue A tile + W[0] tile
    for (int ch = lch0; ch < 16; ch += 4)
        cpa16(sA + lrow * 272 + ch * 16, g_inph + ((size_t)(m0 + lrow) * DMODEL + ch * 8));
    for (int ch = lch0; ch < 17; ch += 4)
        cpa16(sW0 + lrow * 272 + ch * 16, g_Wh4 + (lrow * 136 + ch * 8));
    CPA_COMMIT();
    CPA_WAIT0();
    __syncthreads();

    const int mrow = (warp >> 1) * 16;
    const int nc0  = (warp & 1) * 64;

    #pragma unroll
    for (int t = 0; t < 4; t++) {
        // Prefetch next weight tile into the other buffer (overlaps with MMA below)
        if (t < 3) {
            uint32_t dstW = ((t + 1) & 1) ? sW1 : sW0;
            const __half* srcW = g_Wh4 + (t + 1) * 128 * 136;
            for (int ch = lch0; ch < 17; ch += 4)
                cpa16(dstW + lrow * 272 + ch * 16, srcW + (lrow * 136 + ch * 8));
            CPA_COMMIT();
        }

        const __half* Wh = (t & 1) ? Wb1 : Wb0;
        float acc[8][4];
        #pragma unroll
        for (int j = 0; j < 8; j++) { acc[j][0] = acc[j][1] = acc[j][2] = acc[j][3] = 0.f; }

        #pragma unroll
        for (int k0 = 0; k0 < 128; k0 += 16) {
            unsigned a0 = *(const unsigned*)&Ah[(mrow + gid)     * 136 + k0 + 2 * tg];
            unsigned a1 = *(const unsigned*)&Ah[(mrow + gid + 8) * 136 + k0 + 2 * tg];
            unsigned a2 = *(const unsigned*)&Ah[(mrow + gid)     * 136 + k0 + 2 * tg + 8];
            unsigned a3 = *(const unsigned*)&Ah[(mrow + gid + 8) * 136 + k0 + 2 * tg + 8];
            #pragma unroll
            for (int j = 0; j < 8; j++) {
                unsigned b0 = *(const unsigned*)&Wh[(nc0 + j * 8 + gid) * 136 + k0 + 2 * tg];
                unsigned b1 = *(const unsigned*)&Wh[(nc0 + j * 8 + gid) * 136 + k0 + 2 * tg + 8];
                MMA_F16(acc[j], a0, a1, a2, a3, b0, b1);
            }
        }

        float* Tout = g_T + (size_t)t * N_NODES * DMODEL;
        int r0 = m0 + mrow + gid, r1 = r0 + 8;
        #pragma unroll
        for (int j = 0; j < 8; j++) {
            int col = nc0 + j * 8 + 2 * tg;
            if (r0 < N_NODES)
                *reinterpret_cast<float2*>(&Tout[(size_t)r0 * DMODEL + col]) =
                    make_float2(acc[j][0], acc[j][1]);
            if (r1 < N_NODES)
                *reinterpret_cast<float2*>(&Tout[(size_t)r1 * DMODEL + col]) =
                    make_float2(acc[j][2], acc[j][3]);
        }

        CPA_WAIT0();
        __syncthreads();
    }
}

// ---- edge phase (round-5 version, REDG-bound; CSR planned next) ----
#define EDGES_PER_WARP 2
__global__ __launch_bounds__(256) void edge_kernel(
    const int* __restrict__ deprel, const int* __restrict__ deparc,
    const int* __restrict__ eidx,
    const float* __restrict__ b_in, const float* __restrict__ b_out,
    const float* __restrict__ bg_in, const float* __restrict__ bg_out,
    float* __restrict__ out)
{
    int w = (int)((blockIdx.x * blockDim.x + threadIdx.x) >> 5);
    int lane = threadIdx.x & 31;
    int e0 = w * EDGES_PER_WARP;

    int   t[EDGES_PER_WARP], rel[EDGES_PER_WARP], tgt[EDGES_PER_WARP];
    float4 v[EDGES_PER_WARP];
    float  gpre[EDGES_PER_WARP];
    bool   ok[EDGES_PER_WARP];

    #pragma unroll
    for (int q = 0; q < EDGES_PER_WARP; q++) {
        int e = e0 + q;
        ok[q] = (e < N_EDGES);
        if (ok[q]) {
            t[q]   = __ldg(&deparc[e]);
            rel[q] = __ldg(&deprel[e]);
            int src = __ldg(&eidx[e]);
            tgt[q] = __ldg(&eidx[N_EDGES + e]);
            const float* trow = g_T + ((size_t)t[q] * N_NODES + src) * DMODEL;
            v[q] = reinterpret_cast<const float4*>(trow)[lane];
            gpre[q] = g_G[t[q] * N_NODES + src];
        }
    }

    #pragma unroll
    for (int q = 0; q < EDGES_PER_WARP; q++) {
        if (!ok[q]) continue;
        float4 b = make_float4(0.f, 0.f, 0.f, 0.f);
        if (t[q] == 0) {
            b = reinterpret_cast<const float4*>(b_in)[rel[q] * 32 + lane];
            gpre[q] += bg_in[rel[q]];
        } else if (t[q] == 1) {
            b = reinterpret_cast<const float4*>(b_out)[rel[q] * 32 + lane];
            gpre[q] += bg_out[rel[q]];
        }
        float g = 1.f / (1.f + __expf(-gpre[q]));
        float4 r;
        r.x = (v[q].x + b.x) * g;
        r.y = (v[q].y + b.y) * g;
        r.z = (v[q].z + b.z) * g;
        r.w = (v[q].w + b.w) * g;
        float* dst = out + (size_t)tgt[q] * DMODEL + lane * 4;
        asm volatile("red.global.add.v4.f32 [%0], {%1,%2,%3,%4};"
                     :: "l"(dst), "f"(r.x), "f"(r.y), "f"(r.z), "f"(r.w)
                     : "memory");
    }
}

extern "C" void kernel_launch(void* const* d_in, const int* in_sizes, int n_in,
                              void* d_out, int out_size)
{
    const float* inp       = (const float*)d_in[0];
    const int*   deprel    = (const int*)d_in[1];
    const int*   deparc    = (const int*)d_in[2];
    const int*   eidx      = (const int*)d_in[3];
    const float* V_in      = (const float*)d_in[4];
    const float* b_in      = (const float*)d_in[5];
    const float* V_in_g    = (const float*)d_in[6];
    const float* b_in_g    = (const float*)d_in[7];
    const float* V_out     = (const float*)d_in[8];
    const float* b_out     = (const float*)d_in[9];
    const float* V_out_g   = (const float*)d_in[10];
    const float* b_out_g   = (const float*)d_in[11];
    const float* W_self    = (const float*)d_in[12];
    const float* W_self_g  = (const float*)d_in[13];
    const float* W_norel   = (const float*)d_in[14];
    const float* W_norel_g = (const float*)d_in[15];
    float* out = (float*)d_out;

    const int smem = 34816 * 3;   // Ah + 2x W buffers = 104448 B
    cudaFuncSetAttribute(transform_kernel,
                         cudaFuncAttributeMaxDynamicSharedMemorySize, smem);

    cudaMemsetAsync(d_out, 0, (size_t)out_size * sizeof(float));

    prep_weights_kernel<<<16, 256>>>(V_in, V_out, W_self, W_norel);
    prep_nodes_kernel<<<(N_NODES + 7) / 8, 256>>>(inp, V_in_g, V_out_g, W_self_g, W_norel_g);

    transform_kernel<<<N_PAD / 128, 512, smem>>>();

    const int warps_needed = (N_EDGES + EDGES_PER_WARP - 1) / EDGES_PER_WARP;
    edge_kernel<<<(warps_needed * 32 + 255) / 256, 256>>>(
        deprel, deparc, eidx, b_in, b_out, b_in_g, b_out_g, out);
}